// round 1
// baseline (speedup 1.0000x reference)
#include <cuda_runtime.h>

// ---------------------------------------------------------------------------
// CliffordPC — Cl(3,0) predictive coding, algebraically collapsed.
//
// gp(x, W) == reshape(x,[B,Din*8]) @ What, with
//   What[(j,a),(i,c)] = sign(a, a^c) * W[i, j, a^c]     (forward)
//   Whatr[(j,a),(i,c)] = sign(a, a^c)*REV[a^c]*W[j, i, a^c]   (reverse+transpose)
//
// Per iteration (exact refactor of the reference):
//   grad1 = clip( [H1|H2] @ K1  -  XR ),  H1' = H1 - a*grad1
//        K1 = [[M1 + I], [-What2]],  M1 = What1 @ What1r,  XR = x @ What1r
//   grad2 = clip( [H1'|H2] @ K2 ),        H2' = H2 - a*grad2
//        K2 = [[-What2r], [M2]],     M2 = What2 @ What2r
// ---------------------------------------------------------------------------

namespace {

constexpr float ALPHA_C = 0.01f;

// scratch (static device globals: allocation-free)
__device__ float g_W1e [1024u * 2048u];   // What1  [1024,2048]
__device__ float g_W1re[2048u * 1024u];   // What1r [2048,1024]
__device__ float g_K1  [1536u * 1024u];   // [[M1+I],[-What2]]
__device__ float g_K2  [1536u * 512u];    // [[-What2r],[M2]]
__device__ float g_XR  [4096u * 1024u];   // x @ What1r
__device__ float g_H1a [4096u * 1024u];
__device__ float g_H1b [4096u * 1024u];
__device__ float g_H2a [4096u * 512u];
__device__ float g_H2b [4096u * 512u];

__device__ __forceinline__ int reorder_sign(int a, int b) {
    int s = 0;
    int aa = a >> 1;
    while (aa) { s += __popc(aa & b); aa >>= 1; }
    return (s & 1) ? -1 : 1;
}

__device__ __forceinline__ unsigned long long pack2(float x, float y) {
    unsigned long long r;
    asm("mov.b64 %0, {%1, %2};" : "=l"(r) : "f"(x), "f"(y));
    return r;
}
__device__ __forceinline__ float2 unpack2(unsigned long long v) {
    float2 f;
    asm("mov.b64 {%0, %1}, %2;" : "=f"(f.x), "=f"(f.y) : "l"(v));
    return f;
}

// Expand W [I,J,8] (fwd) or W [J,I,8] (rev) into out [J*8, I*8], scaled by sgn.
__global__ void expand_kernel(const float* __restrict__ W, int J, int I,
                              float* __restrict__ out, int rev, float sgn)
{
    int total = J * 8 * I * 8;
    int idx = blockIdx.x * blockDim.x + threadIdx.x;
    if (idx >= total) return;
    int ncol = I * 8;
    int col = idx % ncol;
    int row = idx / ncol;
    int a = row & 7, j = row >> 3;
    int c = col & 7, i = col >> 3;
    int e = a ^ c;
    float s = (float)reorder_sign(a, e) * sgn;
    size_t widx;
    if (rev) {
        int k = __popc(e);
        if ((k * (k - 1) / 2) & 1) s = -s;            // reverse sign per blade grade
        widx = (size_t)j * ncol + (size_t)i * 8 + e;  // W[j,i,e], W is [J,I,8]
    } else {
        widx = (size_t)i * (size_t)(J * 8) + (size_t)j * 8 + e; // W[i,j,e], W is [I,J,8]
    }
    out[idx] = s * W[widx];
}

// ---------------------------------------------------------------------------
// 128x128x16 fp32 GEMM with packed f32x2 FMAs, split-A (concat along K),
// fused epilogues.
//   EPI 0: C = acc
//   EPI 1: C = acc + I (identity on global row==col)
//   EPI 2: g = clip(acc - XR); C = Hold - ALPHA*g   (grad1 / H1 update)
//   EPI 3: g = clip(acc);      C = Hold - ALPHA*g   (grad2 / H2 update)
// ---------------------------------------------------------------------------
template <int EPI>
__global__ __launch_bounds__(256)
void gemm128(const float* __restrict__ A0, const float* __restrict__ A1,
             int lda0, int lda1, int ksplit,
             const float* __restrict__ Bm, int ldb,
             float* __restrict__ C, int ldc, int K,
             const float* __restrict__ XRp,
             const float* __restrict__ Hold, int ldh)
{
    __shared__ float As[16][132];
    __shared__ float Ws[16][132];

    const int m0 = blockIdx.y * 128;
    const int n0 = blockIdx.x * 128;
    const int tid = threadIdx.x;
    const int tr = tid >> 4;   // 0..15
    const int tc = tid & 15;   // 0..15

    unsigned long long acc[8][4];
#pragma unroll
    for (int i = 0; i < 8; ++i)
#pragma unroll
        for (int j = 0; j < 4; ++j) acc[i][j] = 0ull;

    for (int kt = 0; kt < K; kt += 16) {
        // ---- A tile: 128 rows x 16 k, from whichever K-segment this tile is in
        const float* Ab;
        int lda, kk;
        if (kt < ksplit) { Ab = A0; lda = lda0; kk = kt; }
        else             { Ab = A1; lda = lda1; kk = kt - ksplit; }
#pragma unroll
        for (int u = 0; u < 2; ++u) {
            int f = tid + u * 256;           // float4 id (0..511)
            int row = f >> 2;                // 0..127
            int kc4 = (f & 3) * 4;           // 0,4,8,12
            float4 v = *reinterpret_cast<const float4*>(
                Ab + (size_t)(m0 + row) * lda + kk + kc4);
            As[kc4 + 0][row] = v.x;
            As[kc4 + 1][row] = v.y;
            As[kc4 + 2][row] = v.z;
            As[kc4 + 3][row] = v.w;
        }
        // ---- B tile: 16 k x 128 cols
#pragma unroll
        for (int u = 0; u < 2; ++u) {
            int f = tid + u * 256;
            int brow = f >> 5;               // 0..15
            int bc4  = (f & 31) * 4;         // 0..124
            *reinterpret_cast<float4*>(&Ws[brow][bc4]) =
                *reinterpret_cast<const float4*>(Bm + (size_t)(kt + brow) * ldb + n0 + bc4);
        }
        __syncthreads();

#pragma unroll
        for (int k = 0; k < 16; ++k) {
            float4 a0 = *reinterpret_cast<const float4*>(&As[k][tr * 8]);
            float4 a1 = *reinterpret_cast<const float4*>(&As[k][tr * 8 + 4]);
            float4 b0 = *reinterpret_cast<const float4*>(&Ws[k][tc * 8]);
            float4 b1 = *reinterpret_cast<const float4*>(&Ws[k][tc * 8 + 4]);
            unsigned long long bb0 = pack2(b0.x, b0.y);
            unsigned long long bb1 = pack2(b0.z, b0.w);
            unsigned long long bb2 = pack2(b1.x, b1.y);
            unsigned long long bb3 = pack2(b1.z, b1.w);
            float av[8] = {a0.x, a0.y, a0.z, a0.w, a1.x, a1.y, a1.z, a1.w};
#pragma unroll
            for (int i = 0; i < 8; ++i) {
                unsigned long long aa = pack2(av[i], av[i]);
                asm("fma.rn.f32x2 %0, %1, %2, %0;" : "+l"(acc[i][0]) : "l"(aa), "l"(bb0));
                asm("fma.rn.f32x2 %0, %1, %2, %0;" : "+l"(acc[i][1]) : "l"(aa), "l"(bb1));
                asm("fma.rn.f32x2 %0, %1, %2, %0;" : "+l"(acc[i][2]) : "l"(aa), "l"(bb2));
                asm("fma.rn.f32x2 %0, %1, %2, %0;" : "+l"(acc[i][3]) : "l"(aa), "l"(bb3));
            }
        }
        __syncthreads();
    }

    // ---- epilogue
#pragma unroll
    for (int i = 0; i < 8; ++i) {
        int row = m0 + tr * 8 + i;
#pragma unroll
        for (int jp = 0; jp < 4; ++jp) {
            float2 v = unpack2(acc[i][jp]);
            int col = n0 + tc * 8 + jp * 2;
            size_t o = (size_t)row * ldc + col;
            if (EPI == 0) {
                *reinterpret_cast<float2*>(&C[o]) = v;
            } else if (EPI == 1) {
                v.x += (row == col)     ? 1.0f : 0.0f;
                v.y += (row == col + 1) ? 1.0f : 0.0f;
                *reinterpret_cast<float2*>(&C[o]) = v;
            } else if (EPI == 2) {
                size_t xo = (size_t)row * 1024 + col;
                float gx = fminf(fmaxf(v.x - XRp[xo],     -1.0f), 1.0f);
                float gy = fminf(fmaxf(v.y - XRp[xo + 1], -1.0f), 1.0f);
                size_t ho = (size_t)row * ldh + col;
                float2 r;
                r.x = Hold[ho]     - ALPHA_C * gx;
                r.y = Hold[ho + 1] - ALPHA_C * gy;
                *reinterpret_cast<float2*>(&C[o]) = r;
            } else {
                float gx = fminf(fmaxf(v.x, -1.0f), 1.0f);
                float gy = fminf(fmaxf(v.y, -1.0f), 1.0f);
                size_t ho = (size_t)row * ldh + col;
                float2 r;
                r.x = Hold[ho]     - ALPHA_C * gx;
                r.y = Hold[ho + 1] - ALPHA_C * gy;
                *reinterpret_cast<float2*>(&C[o]) = r;
            }
        }
    }
}

} // namespace

extern "C" void kernel_launch(void* const* d_in, const int* in_sizes, int n_in,
                              void* d_out, int out_size)
{
    // Identify inputs by element count (robust to ordering).
    const float *x = nullptr, *W1 = nullptr, *W2 = nullptr, *h1 = nullptr, *h2 = nullptr;
    for (int i = 0; i < n_in; ++i) {
        switch (in_sizes[i]) {
            case 8388608: x  = (const float*)d_in[i]; break; // [4096,256,8]
            case 262144:  W1 = (const float*)d_in[i]; break; // [256,128,8]
            case 65536:   W2 = (const float*)d_in[i]; break; // [128,64,8]
            case 4194304: h1 = (const float*)d_in[i]; break; // [4096,128,8]
            case 2097152: h2 = (const float*)d_in[i]; break; // [4096,64,8]
        }
    }
    float* out = (float*)d_out;

    float *W1e, *W1re, *K1, *K2, *XR, *H1a, *H1b, *H2a, *H2b;
    cudaGetSymbolAddress((void**)&W1e,  g_W1e);
    cudaGetSymbolAddress((void**)&W1re, g_W1re);
    cudaGetSymbolAddress((void**)&K1,   g_K1);
    cudaGetSymbolAddress((void**)&K2,   g_K2);
    cudaGetSymbolAddress((void**)&XR,   g_XR);
    cudaGetSymbolAddress((void**)&H1a,  g_H1a);
    cudaGetSymbolAddress((void**)&H1b,  g_H1b);
    cudaGetSymbolAddress((void**)&H2a,  g_H2a);
    cudaGetSymbolAddress((void**)&H2b,  g_H2b);

    const int NOSPLIT = 0x40000000;

    // ---- weight expansion
    expand_kernel<<<(1024 * 2048 + 255) / 256, 256>>>(W1, 128, 256, W1e, 0,  1.0f);
    expand_kernel<<<(2048 * 1024 + 255) / 256, 256>>>(W1, 256, 128, W1re, 1, 1.0f);
    // K1 lower block = -What2  [512,1024]
    expand_kernel<<<(512 * 1024 + 255) / 256, 256>>>(W2, 64, 128, K1 + 1024 * 1024, 0, -1.0f);
    // K2 upper block = -What2r [1024,512]
    expand_kernel<<<(1024 * 512 + 255) / 256, 256>>>(W2, 128, 64, K2, 1, -1.0f);

    // ---- M1 + I -> K1 top  ([1024,1024], K=2048)
    gemm128<1><<<dim3(1024 / 128, 1024 / 128), 256>>>(
        W1e, nullptr, 2048, 0, NOSPLIT, W1re, 1024, K1, 1024, 2048, nullptr, nullptr, 0);
    // ---- M2 -> K2 bottom: (-What2) @ (-What2r) = What2 @ What2r  ([512,512], K=1024)
    gemm128<0><<<dim3(512 / 128, 512 / 128), 256>>>(
        K1 + 1024 * 1024, nullptr, 1024, 0, NOSPLIT, K2, 512, K2 + 1024 * 512, 512, 1024,
        nullptr, nullptr, 0);
    // ---- XR = x @ What1r  ([4096,1024], K=2048)
    gemm128<0><<<dim3(1024 / 128, 4096 / 128), 256>>>(
        x, nullptr, 2048, 0, NOSPLIT, W1re, 1024, XR, 1024, 2048, nullptr, nullptr, 0);

    // ---- init: out[0] = x (unchanged state), state buffers
    cudaMemcpyAsync(out, x, (size_t)4096 * 2048 * sizeof(float), cudaMemcpyDeviceToDevice, 0);
    cudaMemcpyAsync(H1a, h1, (size_t)4096 * 1024 * sizeof(float), cudaMemcpyDeviceToDevice, 0);
    cudaMemcpyAsync(H2a, h2, (size_t)4096 * 512 * sizeof(float), cudaMemcpyDeviceToDevice, 0);

    float* H1c = H1a; float* H1n = H1b;
    float* H2c = H2a; float* H2n = H2b;
    for (int it = 0; it < 20; ++it) {
        // H1' = H1 - a*clip([H1|H2]@K1 - XR)
        gemm128<2><<<dim3(1024 / 128, 4096 / 128), 256>>>(
            H1c, H2c, 1024, 512, 1024, K1, 1024, H1n, 1024, 1536, XR, H1c, 1024);
        // H2' = H2 - a*clip([H1'|H2]@K2)
        gemm128<3><<<dim3(512 / 128, 4096 / 128), 256>>>(
            H1n, H2c, 1024, 512, 1024, K2, 512, H2n, 512, 1536, nullptr, H2c, 512);
        float* t;
        t = H1c; H1c = H1n; H1n = t;
        t = H2c; H2c = H2n; H2n = t;
    }

    // ---- final outputs
    cudaMemcpyAsync(out + (size_t)4096 * 2048, H1c,
                    (size_t)4096 * 1024 * sizeof(float), cudaMemcpyDeviceToDevice, 0);
    cudaMemcpyAsync(out + (size_t)4096 * 2048 + (size_t)4096 * 1024, H2c,
                    (size_t)4096 * 512 * sizeof(float), cudaMemcpyDeviceToDevice, 0);
}